// round 4
// baseline (speedup 1.0000x reference)
#include <cuda_runtime.h>
#include <math.h>

#define D_DIM 3072
#define C_DIM 10
#define B_DIM 4096
#define R_ROWS 2                           // rows per warp
#define QUARTERS 4
#define D_Q (D_DIM / QUARTERS)             // 768
#define WARPS 8
#define BLOCK (WARPS * 32)                 // 256
#define ROWS_PER_BLOCK 4                   // 2 row-pairs x 4 quarters = 8 warps
#define GRIDM (B_DIM / ROWS_PER_BLOCK)     // 1024 blocks

#define EPS_REG 0.1f
#define NUM_STAB 1e-6f

// scratch (no cudaMalloc allowed)
__device__ __align__(16) float g_Wt[C_DIM * D_DIM];   // W transposed [C][D]
__device__ float g_M[C_DIM * C_DIM];                  // M = W^T W
__device__ float g_partials[GRIDM];
__device__ unsigned int g_count = 0;                  // reset by last block each call

// ---- packed fp32x2 helpers (sm_103a FFMA2 path) ----
__device__ __forceinline__ unsigned long long ffma2(unsigned long long a,
                                                    unsigned long long b,
                                                    unsigned long long c) {
    unsigned long long d;
    asm("fma.rn.f32x2 %0, %1, %2, %3;" : "=l"(d) : "l"(a), "l"(b), "l"(c));
    return d;
}
__device__ __forceinline__ unsigned long long pk2(float a, float b) {
    unsigned long long r;
    asm("mov.b64 %0, {%1, %2};" : "=l"(r) : "f"(a), "f"(b));
    return r;
}
__device__ __forceinline__ float unpk_sum(unsigned long long v) {
    float lo, hi;
    asm("mov.b64 {%0, %1}, %2;" : "=f"(lo), "=f"(hi) : "l"(v));
    return lo + hi;
}

// ---------------------------------------------------------------------------
// Prep: 120 blocks x 256 threads. Exact-fit transpose of W into g_Wt.
// Blocks 0..99 also compute one entry of M = W^T W each.
// ---------------------------------------------------------------------------
__global__ __launch_bounds__(256) void prep_kernel(const float* __restrict__ W) {
    const int idx = blockIdx.x * 256 + threadIdx.x;      // < 30720 always
    {
        int j = idx / D_DIM;
        int d = idx - j * D_DIM;
        g_Wt[idx] = W[d * C_DIM + j];
    }
    if (blockIdx.x >= C_DIM * C_DIM) return;

    const int j1 = blockIdx.x / C_DIM;
    const int j2 = blockIdx.x % C_DIM;

    float partial = 0.f;
    #pragma unroll 4
    for (int d = threadIdx.x; d < D_DIM; d += 256)
        partial = fmaf(W[d * C_DIM + j1], W[d * C_DIM + j2], partial);

    #pragma unroll
    for (int off = 16; off; off >>= 1)
        partial += __shfl_xor_sync(0xffffffffu, partial, off);

    __shared__ float sw[8];
    int lane = threadIdx.x & 31, w = threadIdx.x >> 5;
    if (lane == 0) sw[w] = partial;
    __syncthreads();
    if (threadIdx.x == 0) {
        float s = 0.f;
        #pragma unroll
        for (int k = 0; k < 8; k++) s += sw[k];
        g_M[blockIdx.x] = s;
    }
}

// ---------------------------------------------------------------------------
// Main: warp = (row-pair, D-quarter). warpId = quarter*2 + rp.
// FFMA2 inner loop with explicit x prefetch. Quarters combined via smem.
// Analytic Jacobian epilogue; fused deterministic final reduction.
// ---------------------------------------------------------------------------
__global__ __launch_bounds__(BLOCK, 3) void main_kernel(const float* __restrict__ data,
                                                        float* __restrict__ out) {
    __shared__ float sM[C_DIM * C_DIM];
    __shared__ float sAcc[WARPS][R_ROWS * C_DIM];
    __shared__ float sWarpSum[WARPS];
    __shared__ bool  sIsLast;
    if (threadIdx.x < C_DIM * C_DIM) sM[threadIdx.x] = g_M[threadIdx.x];

    const int warpId  = threadIdx.x >> 5;
    const int lane    = threadIdx.x & 31;
    const int rp      = warpId & 1;          // row-pair within block
    const int quarter = warpId >> 1;         // D quarter
    const int row0    = blockIdx.x * ROWS_PER_BLOCK + rp * R_ROWS;

    const float* xbase = data + (size_t)row0 * D_DIM + quarter * D_Q + lane * 4;
    const float* wbase = g_Wt + quarter * D_Q + lane * 4;

    unsigned long long acc2[R_ROWS][C_DIM];
    #pragma unroll
    for (int r = 0; r < R_ROWS; r++)
        #pragma unroll
        for (int j = 0; j < C_DIM; j++) acc2[r][j] = 0ULL;

    const int NIT = D_Q / 128;               // 6
    float4 xa = __ldcs(reinterpret_cast<const float4*>(xbase));
    float4 xb = __ldcs(reinterpret_cast<const float4*>(xbase + D_DIM));

    #pragma unroll
    for (int it = 0; it < NIT; it++) {
        unsigned long long xl0 = pk2(xa.x, xa.y), xh0 = pk2(xa.z, xa.w);
        unsigned long long xl1 = pk2(xb.x, xb.y), xh1 = pk2(xb.z, xb.w);
        if (it + 1 < NIT) {                  // prefetch next iteration's x
            xa = __ldcs(reinterpret_cast<const float4*>(xbase + (it + 1) * 128));
            xb = __ldcs(reinterpret_cast<const float4*>(xbase + D_DIM + (it + 1) * 128));
        }
        #pragma unroll
        for (int j = 0; j < C_DIM; j++) {
            float4 wf = *reinterpret_cast<const float4*>(wbase + j * D_DIM + it * 128);
            unsigned long long wl = pk2(wf.x, wf.y);
            unsigned long long wh = pk2(wf.z, wf.w);
            acc2[0][j] = ffma2(xh0, wh, ffma2(xl0, wl, acc2[0][j]));
            acc2[1][j] = ffma2(xh1, wh, ffma2(xl1, wl, acc2[1][j]));
        }
    }

    // horizontal add + warp butterfly reduce (20 values)
    #pragma unroll
    for (int r = 0; r < R_ROWS; r++)
        #pragma unroll
        for (int j = 0; j < C_DIM; j++) {
            float v = unpk_sum(acc2[r][j]);
            #pragma unroll
            for (int off = 16; off; off >>= 1)
                v += __shfl_xor_sync(0xffffffffu, v, off);
            if (lane == 0) sAcc[warpId][r * C_DIM + j] = v;
        }
    __syncthreads();

    float reg = 0.f;
    if (quarter == 0 && lane < R_ROWS) {
        // combine the 4 quarters for this row-pair; lane r handles row row0+r
        const float ALPHA = 1.0f - (float)C_DIM * NUM_STAB;
        float z[C_DIM];
        #pragma unroll
        for (int j = 0; j < C_DIM; j++) {
            float v = 0.f;
            #pragma unroll
            for (int q = 0; q < QUARTERS; q++)
                v += sAcc[q * 2 + rp][lane * C_DIM + j];
            z[j] = v;
        }

        float zmax = z[0];
        #pragma unroll
        for (int j = 1; j < C_DIM; j++) zmax = fmaxf(zmax, z[j]);

        float e[C_DIM], S = 0.f;
        #pragma unroll
        for (int j = 0; j < C_DIM; j++) { e[j] = expf(z[j] - zmax); S += e[j]; }
        const float invS = 1.f / S;

        float sig[C_DIM], p[C_DIM], s[C_DIM];
        float ssum = 0.f, psum_m = 0.f;
        #pragma unroll
        for (int j = 0; j < C_DIM; j++) {
            sig[j] = e[j] * invS;
            p[j]   = fmaf(ALPHA, sig[j], NUM_STAB);
            s[j]   = sqrtf(p[j]);
            ssum  += s[j];
            if (j < C_DIM - 1) psum_m += p[j];
        }
        const float sL = s[C_DIM - 1];
        const float t  = 1.f / (1.f - sL);

        float arg = ssum * 0.31622776601683794f;     // 1/sqrt(10)
        arg = fminf(1.f, fmaxf(-1.f, arg));
        const float delta = 2.f * acosf(arg);
        const float rho   = (2.f * (1.f - sL) - psum_m) * t;

        // v = M sigma, q = sigma^T M sigma
        float v[C_DIM], q = 0.f;
        #pragma unroll
        for (int k = 0; k < C_DIM; k++) {
            float a = 0.f;
            #pragma unroll
            for (int j = 0; j < C_DIM; j++)
                a = fmaf(sM[k * C_DIM + j], sig[j], a);
            v[k] = a;
            q = fmaf(sig[k], a, q);
        }

        // ||J||_F^2 = sum_i g_i^T M g_i,  g_i = a_i e_i + b_i e_L - (a_i+b_i) sigma
        const float gL = ALPHA * sig[C_DIM - 1] / sL;
        float fro = 0.f;
        #pragma unroll
        for (int i = 0; i < C_DIM - 1; i++) {
            float a = t * ALPHA * sig[i] / s[i];
            float b = s[i] * t * t * gL;
            float c = a + b;
            fro += a * a * sM[i * C_DIM + i]
                 + b * b * sM[C_DIM * C_DIM - 1]
                 + c * c * q
                 + 2.f * a * b * sM[i * C_DIM + (C_DIM - 1)]
                 - 2.f * c * (a * v[i] + b * v[C_DIM - 1]);
        }
        const float jac_norm = sqrtf(fmaxf(fro, 0.f));

        const float xv = jac_norm - delta / (rho * EPS_REG);
        reg = (xv > 0.f) ? xv : (expf(xv) - 1.f);
    }

    // deterministic block reduction (only warps 0,1 carry nonzero reg)
    #pragma unroll
    for (int off = 16; off; off >>= 1)
        reg += __shfl_xor_sync(0xffffffffu, reg, off);
    if (lane == 0) sWarpSum[warpId] = reg;
    __syncthreads();
    if (threadIdx.x == 0) {
        float ssum = 0.f;
        #pragma unroll
        for (int w = 0; w < WARPS; w++) ssum += sWarpSum[w];
        g_partials[blockIdx.x] = ssum;
        __threadfence();
        sIsLast = (atomicAdd(&g_count, 1u) == GRIDM - 1);
    }
    __syncthreads();

    // fused final reduction: last block sums all 1024 partials in fixed order
    if (sIsLast) {
        __threadfence();
        float v = 0.f;
        #pragma unroll
        for (int k = 0; k < GRIDM / BLOCK; k++)          // 4 strided chunks, fixed order
            v += g_partials[k * BLOCK + threadIdx.x];
        #pragma unroll
        for (int off = 16; off; off >>= 1)
            v += __shfl_xor_sync(0xffffffffu, v, off);
        if (lane == 0) sWarpSum[warpId] = v;
        __syncthreads();
        if (threadIdx.x == 0) {
            float ssum = 0.f;
            #pragma unroll
            for (int w = 0; w < WARPS; w++) ssum += sWarpSum[w];
            out[0] = ssum * (1.0f / (float)B_DIM);
            g_count = 0;                                  // reset for next graph replay
        }
    }
}

extern "C" void kernel_launch(void* const* d_in, const int* in_sizes, int n_in,
                              void* d_out, int out_size) {
    const float* data = (const float*)d_in[0];   // [4096, 3072] f32
    const float* W    = (const float*)d_in[1];   // [3072, 10]   f32
    float* out        = (float*)d_out;           // scalar f32

    prep_kernel<<<120, 256>>>(W);
    main_kernel<<<GRIDM, BLOCK>>>(data, out);
}